// round 3
// baseline (speedup 1.0000x reference)
#include <cuda_runtime.h>

// ModulatedDeformConv3d: N=1, C=64, Cout=64, H=W=L=32, 3x3x3, s=1, p=1, d=1, DG=1
// Inputs (metadata order): x[1,64,32,32,32], offset[1,81,32,32,32],
//                          mask[1,27,32,32,32], weight[64,64,3,3,3]
// Output: [1,64,32,32,32] float32

#define C_IN   64
#define C_OUT  64
#define DIM    32
#define P_TOT  (DIM * DIM * DIM)   // 32768
#define KPROD  27
#define NWT    (KPROD * C_IN * C_OUT)

// Scratch: weight transposed to [k][c][co] for coalesced per-tap loads.
__device__ float d_wt[NWT];

__global__ void wt_transpose_kernel(const float* __restrict__ w) {
    int idx = blockIdx.x * blockDim.x + threadIdx.x;
    if (idx >= NWT) return;
    int co = idx & 63;
    int c  = (idx >> 6) & 63;
    int k  = idx >> 12;
    // src: weight[co][c][k]
    d_wt[idx] = w[(co * C_IN + c) * KPROD + k];
}

__global__ __launch_bounds__(256, 4) void dcn3d_kernel(
    const float* __restrict__ x,
    const float* __restrict__ offset,
    const float* __restrict__ mask,
    float* __restrict__ out)
{
    __shared__ float s_w[C_IN * C_OUT];    // [c][co] for current tap (16 KB)
    __shared__ float s_val[C_IN * 64];     // [c][p]  sampled columns  (16 KB)
    __shared__ int   s_idx[8][64];         // corner linear indices per position
    __shared__ float s_wt[8][64];          // corner weights (trilinear*valid*mask)

    const int tid = threadIdx.x;
    const int b   = blockIdx.x;            // 512 tiles of 4x4x4
    const int bh  = b >> 6;
    const int bw  = (b >> 3) & 7;
    const int bl  = b & 7;

    // matmul micro-tile coords: ty -> co group (16), tx -> p group (16)
    const int ty = tid >> 4;
    const int tx = tid & 15;

    float acc[4][4];
    #pragma unroll
    for (int i = 0; i < 4; i++)
        #pragma unroll
        for (int j = 0; j < 4; j++) acc[i][j] = 0.f;

    // Phase A: all 256 threads. Each handles position lp = tid&63 and corner
    // pair d0 = (tid>>6)*2. The 4 groups redundantly load offset/mask for the
    // same position (L1 hits) and split the 8 corners 2-per-group.
    const int lp  = tid & 63;
    const int d0  = (tid >> 6) * 2;
    const int ho  = bh * 4 + (lp >> 4);
    const int wo  = bw * 4 + ((lp >> 2) & 3);
    const int lo  = bl * 4 + (lp & 3);
    const int plin = (ho * DIM + wo) * DIM + lo;

    #pragma unroll 1
    for (int k = 0; k < KPROD; k++) {
        __syncthreads();   // s_w / s_val / s_idx / s_wt free from previous tap

        // ---- stage weight tile [c][co] for tap k (contiguous 16 KB, float4) ----
        {
            const float4* src = (const float4*)(d_wt + k * (C_IN * C_OUT));
            float4* dst = (float4*)s_w;
            #pragma unroll
            for (int r = 0; r < 4; r++)
                dst[tid + r * 256] = src[tid + r * 256];
        }

        // ---- coords + corner weights for 64 positions (256 threads) ----
        {
            const int ki = k / 9;
            const int kj = (k / 3) % 3;
            const int kk = k % 3;
            float ch = offset[(k * 3 + 0) * P_TOT + plin] + (float)(ho - 1 + ki);
            float cw = offset[(k * 3 + 1) * P_TOT + plin] + (float)(wo - 1 + kj);
            float cl = offset[(k * 3 + 2) * P_TOT + plin] + (float)(lo - 1 + kk);
            float m  = mask[k * P_TOT + plin];

            float h0f = floorf(ch), w0f = floorf(cw), l0f = floorf(cl);
            float fh = ch - h0f, fw = cw - w0f, fl = cl - l0f;
            int h0 = (int)h0f, w0 = (int)w0f, l0 = (int)l0f;

            // per-axis (weight, index) for the two taps of each axis bit
            float whv[2] = {1.f - fh, fh};
            float wwv[2] = {1.f - fw, fw};
            float wlv[2] = {1.f - fl, fl};

            #pragma unroll
            for (int dd = 0; dd < 2; dd++) {
                const int d = d0 + dd;
                const int dh = (d >> 2) & 1, dw = (d >> 1) & 1, dl = d & 1;
                int ih = h0 + dh, iw = w0 + dw, il = l0 + dl;
                bool valid = (ih >= 0) & (ih < DIM) & (iw >= 0) & (iw < DIM) &
                             (il >= 0) & (il < DIM);
                float wgt = whv[dh] * wwv[dw] * (wlv[dl] * m);
                int ihc = min(max(ih, 0), DIM - 1);
                int iwc = min(max(iw, 0), DIM - 1);
                int ilc = min(max(il, 0), DIM - 1);
                s_idx[d][lp] = (ihc * DIM + iwc) * DIM + ilc;
                s_wt[d][lp]  = valid ? wgt : 0.f;
            }
        }
        __syncthreads();

        // ---- gather: fill s_val[c][p]; each thread does 16 (c,p) pairs ----
        #pragma unroll
        for (int r = 0; r < 16; r++) {
            int idx = tid + r * 256;
            int c = idx >> 6;
            int p = idx & 63;
            const float* xb = x + c * P_TOT;
            float v = 0.f;
            #pragma unroll
            for (int d = 0; d < 8; d++)
                v += s_wt[d][p] * __ldg(xb + s_idx[d][p]);
            s_val[c * 64 + p] = v;
        }
        __syncthreads();

        // ---- 64x64x64 FFMA accumulate (4co x 4p per thread) ----
        #pragma unroll 16
        for (int c = 0; c < C_IN; c++) {
            float4 wv = *(const float4*)&s_w[c * 64 + ty * 4];
            float4 vv = *(const float4*)&s_val[c * 64 + tx * 4];
            float wr[4] = {wv.x, wv.y, wv.z, wv.w};
            float vr[4] = {vv.x, vv.y, vv.z, vv.w};
            #pragma unroll
            for (int i = 0; i < 4; i++)
                #pragma unroll
                for (int j = 0; j < 4; j++)
                    acc[i][j] += wr[i] * vr[j];
        }
    }

    // ---- write out: 4 co rows x 4 consecutive positions (float4 aligned) ----
    const int p0 = tx * 4;
    const int oho = bh * 4 + (p0 >> 4);
    const int owo = bw * 4 + ((p0 >> 2) & 3);
    const int olo = bl * 4 + (p0 & 3);
    const int pbase = (oho * DIM + owo) * DIM + olo;
    #pragma unroll
    for (int i = 0; i < 4; i++) {
        float4 v = make_float4(acc[i][0], acc[i][1], acc[i][2], acc[i][3]);
        *(float4*)&out[(ty * 4 + i) * P_TOT + pbase] = v;
    }
}

extern "C" void kernel_launch(void* const* d_in, const int* in_sizes, int n_in,
                              void* d_out, int out_size) {
    const float* x      = (const float*)d_in[0];
    const float* offset = (const float*)d_in[1];
    const float* mask   = (const float*)d_in[2];
    const float* weight = (const float*)d_in[3];
    float* out = (float*)d_out;

    wt_transpose_kernel<<<(NWT + 255) / 256, 256>>>(weight);
    dcn3d_kernel<<<512, 256>>>(x, offset, mask, out);
}

// round 5
// speedup vs baseline: 2.3853x; 2.3853x over previous
#include <cuda_runtime.h>

// ModulatedDeformConv3d: N=1, C=64, Cout=64, H=W=L=32, 3x3x3, s=1, p=1, d=1, DG=1
// Inputs (metadata order): x[1,64,32,32,32], offset[1,81,32,32,32],
//                          mask[1,27,32,32,32], weight[64,64,3,3,3]
// Output: [1,64,32,32,32] float32
//
// R5 design:
//  - x pre-transposed to channel-last x_t[p][c]: each trilinear corner gather
//    for all 64 ch is one 256B-contiguous warp load (2 L1tex wavefronts)
//    instead of ~24 scattered lines (R3 measured L1tex 78.6% binding).
//  - packed fma.rn.f32x2 (FFMA2) in both gather accumulate and the 64x64x64
//    contraction: halves FMA-pipe issue (ptxas never emits FFMA2 from C++).

#define C_IN    64
#define C_OUT   64
#define DIM     32
#define P_TOT   (DIM * DIM * DIM)   // 32768
#define KPROD   27
#define NWT     (KPROD * C_IN * C_OUT)
#define VSTRIDE 66                  // padded [c][p] stride (even -> 8B LDS align)

typedef unsigned long long u64;

__device__ __forceinline__ u64 pack2(float lo, float hi) {
    u64 r;
    asm("mov.b64 %0, {%1, %2};" : "=l"(r) : "f"(lo), "f"(hi));
    return r;
}
__device__ __forceinline__ void unpack2(u64 v, float& lo, float& hi) {
    asm("mov.b64 {%0, %1}, %2;" : "=f"(lo), "=f"(hi) : "l"(v));
}
__device__ __forceinline__ void ffma2(u64& d, u64 a, u64 b) {
    asm("fma.rn.f32x2 %0, %1, %2, %0;" : "+l"(d) : "l"(a), "l"(b));
}

// Scratch (device globals — no allocation allowed in kernel_launch).
__device__ float d_wt[NWT];             // weight transposed to [k][c][co]
__device__ float d_xt[C_IN * P_TOT];    // x transposed to [p][c] (channel-last)

__global__ void wt_transpose_kernel(const float* __restrict__ w) {
    int idx = blockIdx.x * blockDim.x + threadIdx.x;
    if (idx >= NWT) return;
    int co = idx & 63;
    int c  = (idx >> 6) & 63;
    int k  = idx >> 12;
    d_wt[idx] = w[(co * C_IN + c) * KPROD + k];   // src: weight[co][c][k]
}

// Tiled transpose: x[c][p] -> d_xt[p][c]. Block (32,8), grid (P_TOT/32, C_IN/32).
__global__ void x_transpose_kernel(const float* __restrict__ x) {
    __shared__ float tile[32][33];
    const int p0 = blockIdx.x * 32;
    const int c0 = blockIdx.y * 32;
    const int tx = threadIdx.x, ty = threadIdx.y;
    #pragma unroll
    for (int i = 0; i < 32; i += 8)
        tile[ty + i][tx] = x[(c0 + ty + i) * P_TOT + p0 + tx];
    __syncthreads();
    #pragma unroll
    for (int i = 0; i < 32; i += 8)
        d_xt[(p0 + ty + i) * C_IN + c0 + tx] = tile[tx][ty + i];
}

__global__ __launch_bounds__(256, 4) void dcn3d_kernel(
    const float* __restrict__ offset,
    const float* __restrict__ mask,
    float* __restrict__ out)
{
    __shared__ float s_w[C_IN * C_OUT];      // [c][co] current tap (16 KB)
    __shared__ float s_val[C_IN * VSTRIDE];  // [c][p] sampled columns (padded)
    __shared__ int   s_idx[8][64];           // corner spatial indices per position
    __shared__ float s_wt[8][64];            // corner weights (trilinear*valid*mask)

    const int tid  = threadIdx.x;
    const int b    = blockIdx.x;             // 512 tiles of 4x4x4
    const int bh   = b >> 6;
    const int bw   = (b >> 3) & 7;
    const int bl   = b & 7;
    const int warp = tid >> 5;
    const int lane = tid & 31;

    // matmul micro-tile coords: ty -> co group (16), tx -> p group (16)
    const int ty = tid >> 4;
    const int tx = tid & 15;

    // packed accumulators: [co_i][p_pair], each holds positions (2j, 2j+1)
    u64 acc2[4][2];
    #pragma unroll
    for (int i = 0; i < 4; i++) {
        acc2[i][0] = 0ull;
        acc2[i][1] = 0ull;
    }

    // Phase A: all 256 threads; position lp = tid&63, corner pair d0.
    const int lp  = tid & 63;
    const int d0  = (tid >> 6) * 2;
    const int ho  = bh * 4 + (lp >> 4);
    const int wo  = bw * 4 + ((lp >> 2) & 3);
    const int lo  = bl * 4 + (lp & 3);
    const int plin = (ho * DIM + wo) * DIM + lo;

    const u64* __restrict__ xt8 = (const u64*)d_xt;   // [p][c/2] channel pairs

    #pragma unroll 1
    for (int k = 0; k < KPROD; k++) {
        __syncthreads();   // all smem free from previous tap

        // ---- stage weight tile [c][co] for tap k (contiguous 16 KB, float4) ----
        {
            const float4* src = (const float4*)(d_wt + k * (C_IN * C_OUT));
            float4* dst = (float4*)s_w;
            #pragma unroll
            for (int r = 0; r < 4; r++)
                dst[tid + r * 256] = src[tid + r * 256];
        }

        // ---- coords + corner weights for 64 positions (256 threads) ----
        {
            const int ki = k / 9;
            const int kj = (k / 3) % 3;
            const int kk = k % 3;
            float ch = offset[(k * 3 + 0) * P_TOT + plin] + (float)(ho - 1 + ki);
            float cw = offset[(k * 3 + 1) * P_TOT + plin] + (float)(wo - 1 + kj);
            float cl = offset[(k * 3 + 2) * P_TOT + plin] + (float)(lo - 1 + kk);
            float m  = mask[k * P_TOT + plin];

            float h0f = floorf(ch), w0f = floorf(cw), l0f = floorf(cl);
            float fh = ch - h0f, fw = cw - w0f, fl = cl - l0f;
            int h0 = (int)h0f, w0 = (int)w0f, l0 = (int)l0f;

            float whv[2] = {1.f - fh, fh};
            float wwv[2] = {1.f - fw, fw};
            float wlv[2] = {1.f - fl, fl};

            #pragma unroll
            for (int dd = 0; dd < 2; dd++) {
                const int d = d0 + dd;
                const int dh = (d >> 2) & 1, dw = (d >> 1) & 1, dl = d & 1;
                int ih = h0 + dh, iw = w0 + dw, il = l0 + dl;
                bool valid = (ih >= 0) & (ih < DIM) & (iw >= 0) & (iw < DIM) &
                             (il >= 0) & (il < DIM);
                float wgt = whv[dh] * wwv[dw] * (wlv[dl] * m);
                int ihc = min(max(ih, 0), DIM - 1);
                int iwc = min(max(iw, 0), DIM - 1);
                int ilc = min(max(il, 0), DIM - 1);
                s_idx[d][lp] = (ihc * DIM + iwc) * DIM + ilc;
                s_wt[d][lp]  = valid ? wgt : 0.f;
            }
        }
        __syncthreads();

        // ---- gather: warp handles 8 positions; lanes = channel pairs ----
        // Corner load = 256B contiguous (64 ch x 4B) -> 2 L1tex wavefronts.
        // Accumulate with packed FFMA2 (wgt duplicated, warp-uniform).
        #pragma unroll 2
        for (int i = 0; i < 8; i++) {
            const int p = warp * 8 + i;
            u64 vacc = 0ull;
            #pragma unroll
            for (int d = 0; d < 8; d++) {
                const int gidx = s_idx[d][p];              // warp-uniform
                const u64 w2   = pack2(s_wt[d][p], s_wt[d][p]);
                const u64 xv   = __ldg(&xt8[gidx * (C_IN / 2) + lane]);
                ffma2(vacc, w2, xv);
            }
            float vx, vy;
            unpack2(vacc, vx, vy);
            s_val[(2 * lane)     * VSTRIDE + p] = vx;
            s_val[(2 * lane + 1) * VSTRIDE + p] = vy;
        }
        __syncthreads();

        // ---- 64x64x64 contraction: 8 FFMA2 per c (4co x 2 pos-pairs) ----
        #pragma unroll 16
        for (int c = 0; c < C_IN; c++) {
            float4 wv = *(const float4*)&s_w[c * 64 + ty * 4];
            u64 v01 = *(const u64*)&s_val[c * VSTRIDE + tx * 4];
            u64 v23 = *(const u64*)&s_val[c * VSTRIDE + tx * 4 + 2];
            u64 w2[4] = { pack2(wv.x, wv.x), pack2(wv.y, wv.y),
                          pack2(wv.z, wv.z), pack2(wv.w, wv.w) };
            #pragma unroll
            for (int i = 0; i < 4; i++) {
                ffma2(acc2[i][0], w2[i], v01);
                ffma2(acc2[i][1], w2[i], v23);
            }
        }
    }

    // ---- write out: 4 co rows x 4 consecutive positions (float4 aligned) ----
    const int p0 = tx * 4;
    const int oho = bh * 4 + (p0 >> 4);
    const int owo = bw * 4 + ((p0 >> 2) & 3);
    const int olo = bl * 4 + (p0 & 3);
    const int pbase = (oho * DIM + owo) * DIM + olo;
    #pragma unroll
    for (int i = 0; i < 4; i++) {
        float4 v;
        unpack2(acc2[i][0], v.x, v.y);
        unpack2(acc2[i][1], v.z, v.w);
        *(float4*)&out[(ty * 4 + i) * P_TOT + pbase] = v;
    }
}

extern "C" void kernel_launch(void* const* d_in, const int* in_sizes, int n_in,
                              void* d_out, int out_size) {
    const float* x      = (const float*)d_in[0];
    const float* offset = (const float*)d_in[1];
    const float* mask   = (const float*)d_in[2];
    const float* weight = (const float*)d_in[3];
    float* out = (float*)d_out;

    wt_transpose_kernel<<<(NWT + 255) / 256, 256>>>(weight);
    {
        dim3 blk(32, 8), grd(P_TOT / 32, C_IN / 32);
        x_transpose_kernel<<<grd, blk>>>(x);
    }
    dcn3d_kernel<<<512, 256>>>(offset, mask, out);
}